// round 1
// baseline (speedup 1.0000x reference)
#include <cuda_runtime.h>

#define B_ 8
#define T_ 512
#define S_ 512
#define K_ 512   // input feature dim (M == N == 512)
#define H_ 128

// Scratch for projected tensors (allowed: __device__ globals, no runtime alloc)
__device__ float g_X1[B_ * T_ * H_];   // query @ W2
__device__ float g_X2[B_ * S_ * H_];   // keys  @ W1

__device__ __forceinline__ float tanh_fast(float x) {
    float y;
    asm("tanh.approx.f32 %0, %1;" : "=f"(y) : "f"(x));
    return y;
}

// ---------------------------------------------------------------------------
// Projection: C[4096][128] = A[4096][512] @ W[512][128], fp32 SIMT GEMM.
// blockIdx.z = 0: X1 = query @ W2 ; z = 1: X2 = keys @ W1
// Block: 32 rows x 128 cols, 256 threads, 4x4 micro-tile per thread.
// ---------------------------------------------------------------------------
__global__ __launch_bounds__(256) void proj_kernel(
    const float* __restrict__ query, const float* __restrict__ keys,
    const float* __restrict__ W1, const float* __restrict__ W2)
{
    __shared__ float sa[32 * 36];    // A tile [32 rows][32 k], stride 36
    __shared__ float sw[32 * 128];   // W tile [32 k][128 c]

    const float* A;
    const float* W;
    float* C;
    if (blockIdx.z == 0) { A = query; W = W2; C = g_X1; }
    else                 { A = keys;  W = W1; C = g_X2; }

    const int r0  = blockIdx.x * 32;
    const int tid = threadIdx.x;

    const int rt = tid >> 5;   // 0..7  -> rows rt*4 .. rt*4+3
    const int ct = tid & 31;   // 0..31 -> cols ct*4 .. ct*4+3

    float acc[4][4] = {};

    for (int k0 = 0; k0 < K_; k0 += 32) {
        // fill sa: 32 rows x 32 k (float4 per thread, coalesced)
        {
            const int kq = tid & 7;     // k chunk: k = kq*4
            const int r  = tid >> 3;    // 0..31
            float4 q = *(const float4*)(A + (size_t)(r0 + r) * K_ + k0 + kq * 4);
            *(float4*)(sa + r * 36 + kq * 4) = q;
        }
        // fill sw: 32 k x 128 c
        {
            const int c  = (tid & 31) * 4;
            const int kr = tid >> 5;    // 0..7
            #pragma unroll
            for (int kk = 0; kk < 32; kk += 8) {
                float4 q = *(const float4*)(W + (size_t)(k0 + kr + kk) * H_ + c);
                *(float4*)(sw + (kr + kk) * H_ + c) = q;
            }
        }
        __syncthreads();

        #pragma unroll 8
        for (int k = 0; k < 32; k++) {
            float av[4];
            #pragma unroll
            for (int i = 0; i < 4; i++) av[i] = sa[(rt * 4 + i) * 36 + k];
            float4 w = *(const float4*)(sw + k * H_ + ct * 4);
            float wv[4] = {w.x, w.y, w.z, w.w};
            #pragma unroll
            for (int i = 0; i < 4; i++)
                #pragma unroll
                for (int j = 0; j < 4; j++)
                    acc[i][j] += av[i] * wv[j];
        }
        __syncthreads();
    }

    #pragma unroll
    for (int i = 0; i < 4; i++) {
        float4 o = make_float4(acc[i][0], acc[i][1], acc[i][2], acc[i][3]);
        *(float4*)(C + (size_t)(r0 + rt * 4 + i) * H_ + ct * 4) = o;
    }
}

// ---------------------------------------------------------------------------
// Score: out[b,t,s] = (1/sqrt(512)) * sum_h v[h] * tanh(X1[b,t,h] + X2[b,s,h])
// Block tile: 64 t x 64 s. X1/X2 tiles stored transposed [h][t] in shared
// (stride 68 -> 16B-aligned float4 rows, conflict-free operand loads).
// 256 threads, 4x4 outputs per thread. MUFU.TANH-bound by design.
// ---------------------------------------------------------------------------
#define PADT 68
#define SMEM_SCORE ((2 * 128 * PADT + 128) * 4)

__global__ __launch_bounds__(256) void score_kernel(
    const float* __restrict__ v, float* __restrict__ out)
{
    extern __shared__ float sh[];
    float* sx1 = sh;                   // [128][PADT]  (h-major, t inner)
    float* sx2 = sh + 128 * PADT;      // [128][PADT]
    float* sv  = sh + 2 * 128 * PADT;  // [128]

    const int b   = blockIdx.z;
    const int t0  = blockIdx.y * 64;
    const int s0  = blockIdx.x * 64;
    const int tid = threadIdx.x;

    if (tid < 128) sv[tid] = v[tid];

    // Fill transposed tiles. Global reads: 512B fully-coalesced per warp.
    // Shared stores: lanes write consecutive t for fixed h row -> conflict-free.
    {
        const int hq = tid & 31;   // h = hq*4 .. hq*4+3
        const int r  = tid >> 5;   // 0..7
        const float* X1p = g_X1 + ((size_t)b * T_ + t0) * H_;
        const float* X2p = g_X2 + ((size_t)b * S_ + s0) * H_;
        #pragma unroll
        for (int rr = 0; rr < 64; rr += 8) {
            const int t = r + rr;
            float4 q1 = *(const float4*)(X1p + (size_t)t * H_ + hq * 4);
            float4 q2 = *(const float4*)(X2p + (size_t)t * H_ + hq * 4);
            sx1[(hq * 4 + 0) * PADT + t] = q1.x;
            sx1[(hq * 4 + 1) * PADT + t] = q1.y;
            sx1[(hq * 4 + 2) * PADT + t] = q1.z;
            sx1[(hq * 4 + 3) * PADT + t] = q1.w;
            sx2[(hq * 4 + 0) * PADT + t] = q2.x;
            sx2[(hq * 4 + 1) * PADT + t] = q2.y;
            sx2[(hq * 4 + 2) * PADT + t] = q2.z;
            sx2[(hq * 4 + 3) * PADT + t] = q2.w;
        }
    }
    __syncthreads();

    const int tr = tid >> 4;   // 0..15 -> t rows tr*4..tr*4+3
    const int sc = tid & 15;   // 0..15 -> s cols sc*4..sc*4+3

    float acc[4][4] = {};

    #pragma unroll 4
    for (int h = 0; h < 128; h++) {
        float4 a  = *(const float4*)(sx1 + h * PADT + tr * 4);
        float4 bb = *(const float4*)(sx2 + h * PADT + sc * 4);
        const float vh = sv[h];
        float av[4] = {a.x, a.y, a.z, a.w};
        float bv[4] = {bb.x, bb.y, bb.z, bb.w};
        #pragma unroll
        for (int i = 0; i < 4; i++)
            #pragma unroll
            for (int j = 0; j < 4; j++)
                acc[i][j] += vh * tanh_fast(av[i] + bv[j]);
    }

    const float inv_scale = 0.04419417382415922f;   // 1/sqrt(512)
    float* op = out + ((size_t)b * T_ + t0) * S_ + s0;
    #pragma unroll
    for (int i = 0; i < 4; i++) {
        float4 o = make_float4(acc[i][0] * inv_scale, acc[i][1] * inv_scale,
                               acc[i][2] * inv_scale, acc[i][3] * inv_scale);
        *(float4*)(op + (size_t)(tr * 4 + i) * S_ + sc * 4) = o;
    }
}

// ---------------------------------------------------------------------------
// Inputs (metadata order): query, keys, W1, W2, v. Output: fp32 (B,T,S).
// ---------------------------------------------------------------------------
extern "C" void kernel_launch(void* const* d_in, const int* in_sizes, int n_in,
                              void* d_out, int out_size)
{
    (void)in_sizes; (void)n_in; (void)out_size;
    const float* query = (const float*)d_in[0];
    const float* keys  = (const float*)d_in[1];
    const float* W1    = (const float*)d_in[2];
    const float* W2    = (const float*)d_in[3];
    const float* v     = (const float*)d_in[4];
    float* out = (float*)d_out;

    cudaFuncSetAttribute(score_kernel,
                         cudaFuncAttributeMaxDynamicSharedMemorySize, SMEM_SCORE);

    // Phase 1: both projections in one grid (z selects tensor pair)
    proj_kernel<<<dim3((B_ * T_) / 32, 1, 2), 256>>>(query, keys, W1, W2);

    // Phase 2: score
    score_kernel<<<dim3(S_ / 64, T_ / 64, B_), 256, SMEM_SCORE>>>(v, out);
}

// round 2
// speedup vs baseline: 1.0025x; 1.0025x over previous
#include <cuda_runtime.h>

#define B_ 8
#define T_ 512
#define S_ 512
#define K_ 512   // input feature dim (M == N == 512)
#define H_ 128

// Scratch for projected tensors (allowed: __device__ globals, no runtime alloc)
__device__ float g_X1[B_ * T_ * H_];   // query @ W2
__device__ float g_X2[B_ * S_ * H_];   // keys  @ W1

__device__ __forceinline__ float tanh_fast(float x) {
    float y;
    asm("tanh.approx.f32 %0, %1;" : "=f"(y) : "f"(x));
    return y;
}

// ---------------------------------------------------------------------------
// Projection: C[4096][128] = A[4096][512] @ W[512][128], fp32 SIMT GEMM.
// blockIdx.z = 0: X1 = query @ W2 ; z = 1: X2 = keys @ W1
// Block: 32 rows x 128 cols, 256 threads, 4x4 micro-tile per thread.
// ---------------------------------------------------------------------------
__global__ __launch_bounds__(256) void proj_kernel(
    const float* __restrict__ query, const float* __restrict__ keys,
    const float* __restrict__ W1, const float* __restrict__ W2)
{
    __shared__ float sa[32 * 36];    // A tile [32 rows][32 k], stride 36
    __shared__ float sw[32 * 128];   // W tile [32 k][128 c]

    const float* A;
    const float* W;
    float* C;
    if (blockIdx.z == 0) { A = query; W = W2; C = g_X1; }
    else                 { A = keys;  W = W1; C = g_X2; }

    const int r0  = blockIdx.x * 32;
    const int tid = threadIdx.x;

    const int rt = tid >> 5;   // 0..7  -> rows rt*4 .. rt*4+3
    const int ct = tid & 31;   // 0..31 -> cols ct*4 .. ct*4+3

    float acc[4][4] = {};

    for (int k0 = 0; k0 < K_; k0 += 32) {
        // fill sa: 32 rows x 32 k (float4 per thread, coalesced)
        {
            const int kq = tid & 7;     // k chunk: k = kq*4
            const int r  = tid >> 3;    // 0..31
            float4 q = *(const float4*)(A + (size_t)(r0 + r) * K_ + k0 + kq * 4);
            *(float4*)(sa + r * 36 + kq * 4) = q;
        }
        // fill sw: 32 k x 128 c
        {
            const int c  = (tid & 31) * 4;
            const int kr = tid >> 5;    // 0..7
            #pragma unroll
            for (int kk = 0; kk < 32; kk += 8) {
                float4 q = *(const float4*)(W + (size_t)(k0 + kr + kk) * H_ + c);
                *(float4*)(sw + (kr + kk) * H_ + c) = q;
            }
        }
        __syncthreads();

        #pragma unroll 8
        for (int k = 0; k < 32; k++) {
            float av[4];
            #pragma unroll
            for (int i = 0; i < 4; i++) av[i] = sa[(rt * 4 + i) * 36 + k];
            float4 w = *(const float4*)(sw + k * H_ + ct * 4);
            float wv[4] = {w.x, w.y, w.z, w.w};
            #pragma unroll
            for (int i = 0; i < 4; i++)
                #pragma unroll
                for (int j = 0; j < 4; j++)
                    acc[i][j] += av[i] * wv[j];
        }
        __syncthreads();
    }

    #pragma unroll
    for (int i = 0; i < 4; i++) {
        float4 o = make_float4(acc[i][0], acc[i][1], acc[i][2], acc[i][3]);
        *(float4*)(C + (size_t)(r0 + rt * 4 + i) * H_ + ct * 4) = o;
    }
}

// ---------------------------------------------------------------------------
// Score: out[b,t,s] = (1/sqrt(512)) * sum_h v[h] * tanh(X1[b,t,h] + X2[b,s,h])
// Block tile: 64 t x 64 s. X1/X2 tiles stored transposed [h][t] in shared
// (stride 68 -> 16B-aligned float4 rows, conflict-free operand loads).
// 256 threads, 4x4 outputs per thread. MUFU.TANH-bound by design.
// ---------------------------------------------------------------------------
#define PADT 68
#define SMEM_SCORE ((2 * 128 * PADT + 128) * 4)

__global__ __launch_bounds__(256) void score_kernel(
    const float* __restrict__ v, float* __restrict__ out)
{
    extern __shared__ float sh[];
    float* sx1 = sh;                   // [128][PADT]  (h-major, t inner)
    float* sx2 = sh + 128 * PADT;      // [128][PADT]
    float* sv  = sh + 2 * 128 * PADT;  // [128]

    const int b   = blockIdx.z;
    const int t0  = blockIdx.y * 64;
    const int s0  = blockIdx.x * 64;
    const int tid = threadIdx.x;

    if (tid < 128) sv[tid] = v[tid];

    // Fill transposed tiles. Global reads: 512B fully-coalesced per warp.
    // Shared stores: lanes write consecutive t for fixed h row -> conflict-free.
    {
        const int hq = tid & 31;   // h = hq*4 .. hq*4+3
        const int r  = tid >> 5;   // 0..7
        const float* X1p = g_X1 + ((size_t)b * T_ + t0) * H_;
        const float* X2p = g_X2 + ((size_t)b * S_ + s0) * H_;
        #pragma unroll
        for (int rr = 0; rr < 64; rr += 8) {
            const int t = r + rr;
            float4 q1 = *(const float4*)(X1p + (size_t)t * H_ + hq * 4);
            float4 q2 = *(const float4*)(X2p + (size_t)t * H_ + hq * 4);
            sx1[(hq * 4 + 0) * PADT + t] = q1.x;
            sx1[(hq * 4 + 1) * PADT + t] = q1.y;
            sx1[(hq * 4 + 2) * PADT + t] = q1.z;
            sx1[(hq * 4 + 3) * PADT + t] = q1.w;
            sx2[(hq * 4 + 0) * PADT + t] = q2.x;
            sx2[(hq * 4 + 1) * PADT + t] = q2.y;
            sx2[(hq * 4 + 2) * PADT + t] = q2.z;
            sx2[(hq * 4 + 3) * PADT + t] = q2.w;
        }
    }
    __syncthreads();

    const int tr = tid >> 4;   // 0..15 -> t rows tr*4..tr*4+3
    const int sc = tid & 15;   // 0..15 -> s cols sc*4..sc*4+3

    float acc[4][4] = {};

    #pragma unroll 4
    for (int h = 0; h < 128; h++) {
        float4 a  = *(const float4*)(sx1 + h * PADT + tr * 4);
        float4 bb = *(const float4*)(sx2 + h * PADT + sc * 4);
        const float vh = sv[h];
        float av[4] = {a.x, a.y, a.z, a.w};
        float bv[4] = {bb.x, bb.y, bb.z, bb.w};
        #pragma unroll
        for (int i = 0; i < 4; i++)
            #pragma unroll
            for (int j = 0; j < 4; j++)
                acc[i][j] += vh * tanh_fast(av[i] + bv[j]);
    }

    const float inv_scale = 0.04419417382415922f;   // 1/sqrt(512)
    float* op = out + ((size_t)b * T_ + t0) * S_ + s0;
    #pragma unroll
    for (int i = 0; i < 4; i++) {
        float4 o = make_float4(acc[i][0] * inv_scale, acc[i][1] * inv_scale,
                               acc[i][2] * inv_scale, acc[i][3] * inv_scale);
        *(float4*)(op + (size_t)(tr * 4 + i) * S_ + sc * 4) = o;
    }
}

// ---------------------------------------------------------------------------
// Inputs (metadata order): query, keys, W1, W2, v. Output: fp32 (B,T,S).
// ---------------------------------------------------------------------------
extern "C" void kernel_launch(void* const* d_in, const int* in_sizes, int n_in,
                              void* d_out, int out_size)
{
    (void)in_sizes; (void)n_in; (void)out_size;
    const float* query = (const float*)d_in[0];
    const float* keys  = (const float*)d_in[1];
    const float* W1    = (const float*)d_in[2];
    const float* W2    = (const float*)d_in[3];
    const float* v     = (const float*)d_in[4];
    float* out = (float*)d_out;

    cudaFuncSetAttribute(score_kernel,
                         cudaFuncAttributeMaxDynamicSharedMemorySize, SMEM_SCORE);

    // Phase 1: both projections in one grid (z selects tensor pair)
    proj_kernel<<<dim3((B_ * T_) / 32, 1, 2), 256>>>(query, keys, W1, W2);

    // Phase 2: score
    score_kernel<<<dim3(S_ / 64, T_ / 64, B_), 256, SMEM_SCORE>>>(v, out);
}